// round 11
// baseline (speedup 1.0000x reference)
#include <cuda_runtime.h>

// CapLayer fused capsule routing. 256 CTAs x 512 threads, 2 CTAs/SM,
// 2 batch elems/CTA (weight loads shared), x served from L1/L2.
// csum reduction deferred to Phase C (raw quad partials in csq).
// x:    d_in[0]  float [512][256][6][6]   (channel = g*8+k, g<32, k<8)
// W:    d_in[2]  float [5120][8] ; flat = g*1280 + j*128 + d*8 + k
// bias: d_in[3]  float [5120]    ; flat = g*160  + j*16  + d
// out:  float [512][10][16]

#define LOG2E 1.4426950408889634f

__device__ float g_WT[40960];   // [g][j][k][d]

struct Smem {
    float cbuf[16][360];  // per-warp c scratch [w][j][hw]
    float scr[16][192];   // per-warp, per-elem 96: [0..79] vW[j][k], [80..89] vb[j]
    float cx[2][2560];    // [e][j][g][k]
    float csq[2][4][320]; // [e][q-partial][j*32+g]  (unreduced csum quads)
    float sWsB[2][320];   // sW=[0..159], sB=[160..319]; xsum aliases [0..255]
    float vsum[2][160];   // LOG2E * accumulated v, [e][j][d]
};                        // 17472 floats = 69888 B (2 CTAs/SM: 139.8KB)

__device__ __forceinline__ float ex2_approx(float x) {
    float y; asm("ex2.approx.ftz.f32 %0, %1;" : "=f"(y) : "f"(x)); return y;
}
__device__ __forceinline__ float rcp_approx(float x) {
    float y; asm("rcp.approx.ftz.f32 %0, %1;" : "=f"(y) : "f"(x)); return y;
}
__device__ __forceinline__ float dot4(float4 a, float4 b) {
    return a.x * b.x + a.y * b.y + a.z * b.z + a.w * b.w;
}
__device__ __forceinline__ float sum4(float4 a) {
    return a.x + a.y + a.z + a.w;
}
__device__ __forceinline__ float4 add4(float4 a, float4 b) {
    return make_float4(a.x + b.x, a.y + b.y, a.z + b.z, a.w + b.w);
}

__global__ void transpose_W_kernel(const float* __restrict__ W) {
    int i = blockIdx.x * 256 + threadIdx.x;
    if (i < 40960) {
        int d = i & 15;
        int k = (i >> 4) & 7;
        int gj = i >> 7;
        int j = gj % 10, g = gj / 10;
        g_WT[i] = W[g * 1280 + j * 128 + d * 8 + k];
    }
}

__global__ __launch_bounds__(512, 2)
void caps_kernel(const float* __restrict__ x_g,
                 const float* __restrict__ W,
                 const float* __restrict__ bias,
                 float* __restrict__ out) {
    extern __shared__ float smem_raw[];
    Smem* S = reinterpret_cast<Smem*>(smem_raw);

    const int b0   = blockIdx.x * 2;
    const int tid  = threadIdx.x;
    const int w    = tid >> 5;
    const int lane = tid & 31;

    const float* x0g = x_g + (size_t)b0 * 9216;
    const float* x1g = x0g + 9216;

    // ---- xsum[e][g][k] = sum_hw x (from global; stored in sWsB alias) ----
    {
        const int e = tid >> 8, idx = tid & 255;
        const float4* p = reinterpret_cast<const float4*>((e ? x1g : x0g) + idx * 36);
        float4 a4 = p[0];
        #pragma unroll
        for (int t = 1; t < 9; t++) a4 = add4(a4, p[t]);
        S->sWsB[e][idx] = sum4(a4);
    }
    __syncthreads();

    // iter 1 shortcut: c uniform 0.1 -> cx = 0.1*xsum (all j)
    for (int i = tid; i < 5120; i += 512) {
        const int e = (i >= 2560);
        const int ii = i - e * 2560;
        S->cx[0][i] = 0.1f * S->sWsB[e][ii & 255];
    }
    __syncthreads();

    for (int it = 0; it < 3; ++it) {
        if (it > 0) {
            // ===== Phase A-pre + A + B; warp handles groups w and w+16 =====
            #pragma unroll
            for (int gi = 0; gi < 2; gi++) {
                const int g = w + gi * 16;
                float* scr = S->scr[w];

                // --- A-pre: shared WT/bias loads for both elements ---
                {
                    const float4* WTv = reinterpret_cast<const float4*>(g_WT) + g * 320;
                    const float4* vs0 = reinterpret_cast<const float4*>(S->vsum[0]);
                    const float4* vs1 = reinterpret_cast<const float4*>(S->vsum[1]);
                    const int q  = lane & 3;
                    const int jk = lane >> 2;
                    #pragma unroll
                    for (int r = 0; r < 10; r++) {
                        float4 a = WTv[r * 32 + lane];       // coalesced 512B
                        float p0 = dot4(a, vs0[r * 4 + q]);
                        float p1 = dot4(a, vs1[r * 4 + q]);
                        p0 += __shfl_xor_sync(0xffffffffu, p0, 1);
                        p0 += __shfl_xor_sync(0xffffffffu, p0, 2);
                        p1 += __shfl_xor_sync(0xffffffffu, p1, 1);
                        p1 += __shfl_xor_sync(0xffffffffu, p1, 2);
                        if (q == 0) { scr[r * 8 + jk] = p0; scr[96 + r * 8 + jk] = p1; }
                    }
                    const float4* Bv = reinterpret_cast<const float4*>(bias);
                    float4 fa = Bv[g * 40 + lane];
                    float4 fb = Bv[g * 40 + 32 + (lane & 7)];
                    float pa0 = dot4(fa, vs0[lane]);
                    float pa1 = dot4(fa, vs1[lane]);
                    float pb0 = dot4(fb, vs0[32 + (lane & 7)]);
                    float pb1 = dot4(fb, vs1[32 + (lane & 7)]);
                    pa0 += __shfl_xor_sync(0xffffffffu, pa0, 1);
                    pa0 += __shfl_xor_sync(0xffffffffu, pa0, 2);
                    pa1 += __shfl_xor_sync(0xffffffffu, pa1, 1);
                    pa1 += __shfl_xor_sync(0xffffffffu, pa1, 2);
                    pb0 += __shfl_xor_sync(0xffffffffu, pb0, 1);
                    pb0 += __shfl_xor_sync(0xffffffffu, pb0, 2);
                    pb1 += __shfl_xor_sync(0xffffffffu, pb1, 1);
                    pb1 += __shfl_xor_sync(0xffffffffu, pb1, 2);
                    if ((lane & 3) == 0) {
                        scr[80 + (lane >> 2)] = pa0;
                        scr[96 + 80 + (lane >> 2)] = pa1;
                        if (lane < 8) {
                            scr[88 + (lane >> 2)] = pb0;
                            scr[96 + 88 + (lane >> 2)] = pb1;
                        }
                    }
                }
                __syncwarp();

                // --- Phase A+B per element ---
                #pragma unroll
                for (int e = 0; e < 2; e++) {
                    const float* se = scr + e * 96;
                    const float* xge = e ? x1g : x0g;
                    // Phase A: logits -> softmax over j -> c
                    {
                        const float* xr = xge + g * 288;
                        float xv[8], xv2[8];
                        #pragma unroll
                        for (int k = 0; k < 8; k++) {
                            xv[k]  = xr[k * 36 + lane];
                            xv2[k] = xr[k * 36 + 32 + (lane & 3)];
                        }
                        // hoisted vb loads (3 vector loads instead of 10 scalars)
                        float4 vb03 = *reinterpret_cast<const float4*>(se + 80);
                        float4 vb47 = *reinterpret_cast<const float4*>(se + 84);
                        float2 vb89 = *reinterpret_cast<const float2*>(se + 88);
                        const float vbs[10] = {vb03.x, vb03.y, vb03.z, vb03.w,
                                               vb47.x, vb47.y, vb47.z, vb47.w,
                                               vb89.x, vb89.y};
                        float bb[10], bb2[10];
                        #pragma unroll
                        for (int j = 0; j < 10; j++) {
                            const float4* vwp = reinterpret_cast<const float4*>(se + j * 8);
                            float4 w0 = vwp[0], w1 = vwp[1];
                            float t0 = vbs[j];
                            float a  = t0, a2 = t0;
                            a  += w0.x*xv[0] + w0.y*xv[1] + w0.z*xv[2] + w0.w*xv[3]
                                + w1.x*xv[4] + w1.y*xv[5] + w1.z*xv[6] + w1.w*xv[7];
                            a2 += w0.x*xv2[0] + w0.y*xv2[1] + w0.z*xv2[2] + w0.w*xv2[3]
                                + w1.x*xv2[4] + w1.y*xv2[5] + w1.z*xv2[6] + w1.w*xv2[7];
                            bb[j] = a; bb2[j] = a2;
                        }
                        float Z = 0.f, Z2 = 0.f;
                        #pragma unroll
                        for (int j = 0; j < 10; j++) {
                            bb[j]  = ex2_approx(bb[j]);   Z  += bb[j];
                            bb2[j] = ex2_approx(bb2[j]);  Z2 += bb2[j];
                        }
                        float r  = rcp_approx(Z);
                        float r2 = rcp_approx(Z2);
                        float* cw = S->cbuf[w];
                        #pragma unroll
                        for (int j = 0; j < 10; j++) {
                            cw[j * 36 + lane] = bb[j] * r;
                            if (lane < 4) cw[j * 36 + 32 + lane] = bb2[j] * r2;
                        }
                    }
                    __syncwarp();
                    // Phase B: cx reduce over q-quad; csum partials stored raw
                    {
                        const int k = lane >> 2, q = lane & 3;
                        const float* xr = xge + (g * 8 + k) * 36;
                        float4 x0 = *reinterpret_cast<const float4*>(xr + 4 * q);
                        float4 x1 = *reinterpret_cast<const float4*>(xr + 16 + 4 * q);
                        float  x2 = xr[32 + q];
                        const float* cb = S->cbuf[w];
                        float acc[10], cs[10];
                        #pragma unroll
                        for (int j = 0; j < 10; j++) {
                            float4 c0 = *reinterpret_cast<const float4*>(cb + j * 36 + 4 * q);
                            float4 c1 = *reinterpret_cast<const float4*>(cb + j * 36 + 16 + 4 * q);
                            float  c2 = cb[j * 36 + 32 + q];
                            acc[j] = dot4(c0, x0) + dot4(c1, x1) + c2 * x2;
                            cs[j]  = sum4(c0) + sum4(c1) + c2;
                        }
                        #pragma unroll
                        for (int j = 0; j < 10; j++) {
                            acc[j] += __shfl_xor_sync(0xffffffffu, acc[j], 1);
                            acc[j] += __shfl_xor_sync(0xffffffffu, acc[j], 2);
                        }
                        if (q == 0) {
                            #pragma unroll
                            for (int j = 0; j < 10; j++) S->cx[e][j * 256 + g * 8 + k] = acc[j];
                        }
                        if (k == 0) {   // lanes (0,q): store raw quad partials
                            #pragma unroll
                            for (int j = 0; j < 10; j++) S->csq[e][q][j * 32 + g] = cs[j];
                        }
                    }
                    __syncwarp();
                }
            }
            __syncthreads();
        }

        // ===== Phase C: shared W/bias loads serve both elements =====
        if (tid < 320) {
            const int p  = tid >> 1;
            const int kh = tid & 1;
            const int j  = p >> 4;
            const float4* Wv   = reinterpret_cast<const float4*>(W);
            const float4* cxv0 = reinterpret_cast<const float4*>(S->cx[0]);
            const float4* cxv1 = reinterpret_cast<const float4*>(S->cx[1]);
            float a00 = 0.f, a01 = 0.f, a10 = 0.f, a11 = 0.f;
            #pragma unroll 8
            for (int g = 0; g < 32; g += 2) {
                float4 w0 = Wv[g * 320 + p * 2 + kh];
                float4 w1 = Wv[(g + 1) * 320 + p * 2 + kh];
                a00 += dot4(w0, cxv0[j * 64 + g * 2 + kh]);
                a01 += dot4(w1, cxv0[j * 64 + (g + 1) * 2 + kh]);
                a10 += dot4(w0, cxv1[j * 64 + g * 2 + kh]);
                a11 += dot4(w1, cxv1[j * 64 + (g + 1) * 2 + kh]);
            }
            float acc0 = a00 + a01, acc1 = a10 + a11;
            acc0 += __shfl_xor_sync(0xffffffffu, acc0, 1);
            acc1 += __shfl_xor_sync(0xffffffffu, acc1, 1);
            if (kh == 0) { S->sWsB[0][p] = acc0; S->sWsB[1][p] = acc1; }
        } else if (tid >= 352) {
            const int p = tid - 352;     // 0..159
            const int j = p >> 4;
            float ab0, ab1;
            if (it == 0) {
                // csum == 3.6 uniformly
                float sb = 0.f;
                #pragma unroll
                for (int gg = 0; gg < 8; gg++) {
                    sb += bias[(gg * 4 + 0) * 160 + p] + bias[(gg * 4 + 1) * 160 + p]
                        + bias[(gg * 4 + 2) * 160 + p] + bias[(gg * 4 + 3) * 160 + p];
                }
                ab0 = ab1 = 3.6f * sb;
            } else {
                const float4* q00 = reinterpret_cast<const float4*>(S->csq[0][0] + j * 32);
                const float4* q01 = reinterpret_cast<const float4*>(S->csq[0][1] + j * 32);
                const float4* q02 = reinterpret_cast<const float4*>(S->csq[0][2] + j * 32);
                const float4* q03 = reinterpret_cast<const float4*>(S->csq[0][3] + j * 32);
                const float4* q10 = reinterpret_cast<const float4*>(S->csq[1][0] + j * 32);
                const float4* q11 = reinterpret_cast<const float4*>(S->csq[1][1] + j * 32);
                const float4* q12 = reinterpret_cast<const float4*>(S->csq[1][2] + j * 32);
                const float4* q13 = reinterpret_cast<const float4*>(S->csq[1][3] + j * 32);
                ab0 = 0.f; ab1 = 0.f;
                #pragma unroll
                for (int gg = 0; gg < 8; gg++) {
                    float4 c40 = add4(add4(q00[gg], q01[gg]), add4(q02[gg], q03[gg]));
                    float4 c41 = add4(add4(q10[gg], q11[gg]), add4(q12[gg], q13[gg]));
                    float bv0 = bias[(gg * 4 + 0) * 160 + p];
                    float bv1 = bias[(gg * 4 + 1) * 160 + p];
                    float bv2 = bias[(gg * 4 + 2) * 160 + p];
                    float bv3 = bias[(gg * 4 + 3) * 160 + p];
                    ab0 += bv0 * c40.x + bv1 * c40.y + bv2 * c40.z + bv3 * c40.w;
                    ab1 += bv0 * c41.x + bv1 * c41.y + bv2 * c41.z + bv3 * c41.w;
                }
            }
            S->sWsB[0][160 + p] = ab0;
            S->sWsB[1][160 + p] = ab1;
        }
        __syncthreads();

        // ===== Phase D: squash + telescoped vsum accumulate =====
        {
            int e = -1, p = 0;
            if (tid < 160) { e = 0; p = tid; }
            else if (tid >= 256 && tid < 416) { e = 1; p = tid - 256; }
            if (e >= 0) {
                float sv = S->sWsB[e][p] + S->sWsB[e][160 + p];
                float n2 = sv * sv;
                n2 += __shfl_xor_sync(0xffffffffu, n2, 1);
                n2 += __shfl_xor_sync(0xffffffffu, n2, 2);
                n2 += __shfl_xor_sync(0xffffffffu, n2, 4);
                n2 += __shfl_xor_sync(0xffffffffu, n2, 8);
                float f  = __fdividef(sqrtf(n2), 1.0f + n2);
                float vv = sv * f;
                if (it == 2) {
                    out[(size_t)(b0 + e) * 160 + p] = vv;
                } else {
                    S->vsum[e][p] = (it == 0) ? LOG2E * vv : S->vsum[e][p] + LOG2E * vv;
                }
            }
        }
        if (it < 2) __syncthreads();
    }
}

extern "C" void kernel_launch(void* const* d_in, const int* in_sizes, int n_in,
                              void* d_out, int out_size) {
    const float* x    = (const float*)d_in[0];
    const float* W    = (const float*)d_in[2];
    const float* bias = (const float*)d_in[3];
    float* out = (float*)d_out;

    transpose_W_kernel<<<160, 256>>>(W);

    cudaFuncSetAttribute(caps_kernel,
                         cudaFuncAttributeMaxDynamicSharedMemorySize,
                         (int)sizeof(Smem));
    caps_kernel<<<256, 512, sizeof(Smem)>>>(x, W, bias, out);
}

// round 12
// speedup vs baseline: 1.0259x; 1.0259x over previous
#include <cuda_runtime.h>

// CapLayer fused capsule routing. 296 CTAs (=148 SMs x 2) x 512 threads.
// CTAs 0..215 process 2 batch elems; 216..295 process 1 (duplicated slot) so
// every SM hosts exactly two co-resident CTAs with uniform work.
// x:    d_in[0]  float [512][256][6][6]   (channel = g*8+k, g<32, k<8)
// W:    d_in[2]  float [5120][8] ; flat = g*1280 + j*128 + d*8 + k
// bias: d_in[3]  float [5120]    ; flat = g*160  + j*16  + d
// out:  float [512][10][16]

#define LOG2E 1.4426950408889634f

__device__ float g_WT[40960];   // [g][j][k][d]

struct Smem {
    float cbuf[16][360];  // per-warp c scratch [w][j][hw]
    float scr[16][192];   // per-warp, per-elem 96: [0..79] vW[j][k], [80..89] vb[j]
    float cx[2][2560];    // [e][j][g][k]
    float csum[2][320];   // [e][j][g]  (filled by B for it>0 only)
    float sWsB[2][320];   // sW=[0..159], sB=[160..319]; xsum aliases [0..255]
    float vsum[2][160];   // LOG2E * accumulated v, [e][j][d]
};                        // 15552 floats = 62208 B (2 CTAs/SM)

__device__ __forceinline__ float ex2_approx(float x) {
    float y; asm("ex2.approx.ftz.f32 %0, %1;" : "=f"(y) : "f"(x)); return y;
}
__device__ __forceinline__ float rcp_approx(float x) {
    float y; asm("rcp.approx.ftz.f32 %0, %1;" : "=f"(y) : "f"(x)); return y;
}
__device__ __forceinline__ float dot4(float4 a, float4 b) {
    return a.x * b.x + a.y * b.y + a.z * b.z + a.w * b.w;
}
__device__ __forceinline__ float sum4(float4 a) {
    return a.x + a.y + a.z + a.w;
}
__device__ __forceinline__ float4 add4(float4 a, float4 b) {
    return make_float4(a.x + b.x, a.y + b.y, a.z + b.z, a.w + b.w);
}

__global__ void transpose_W_kernel(const float* __restrict__ W) {
    int i = blockIdx.x * 256 + threadIdx.x;
    if (i < 40960) {
        int d = i & 15;
        int k = (i >> 4) & 7;
        int gj = i >> 7;
        int j = gj % 10, g = gj / 10;
        g_WT[i] = W[g * 1280 + j * 128 + d * 8 + k];
    }
}

__global__ __launch_bounds__(512, 2)
void caps_kernel(const float* __restrict__ x_g,
                 const float* __restrict__ W,
                 const float* __restrict__ bias,
                 float* __restrict__ out) {
    extern __shared__ float smem_raw[];
    Smem* S = reinterpret_cast<Smem*>(smem_raw);

    const int cta  = blockIdx.x;
    const bool two = (cta < 216);
    const int b0   = two ? cta * 2 : 432 + (cta - 216);
    const int b1   = two ? b0 + 1 : b0;
    const int tid  = threadIdx.x;
    const int w    = tid >> 5;
    const int lane = tid & 31;

    const float* x0g = x_g + (size_t)b0 * 9216;
    const float* x1g = x_g + (size_t)b1 * 9216;

    // ---- xsum[e][g][k] = sum_hw x (from global; stored in sWsB alias) ----
    {
        const int e = tid >> 8, idx = tid & 255;
        const float4* p = reinterpret_cast<const float4*>((e ? x1g : x0g) + idx * 36);
        float4 a4 = p[0];
        #pragma unroll
        for (int t = 1; t < 9; t++) a4 = add4(a4, p[t]);
        S->sWsB[e][idx] = sum4(a4);
    }
    __syncthreads();

    // iter 1 shortcut: c uniform 0.1 -> cx = 0.1*xsum (all j); csum==3.6 handled
    // by the it==0 bias fast path, so no csum init needed.
    for (int i = tid; i < 5120; i += 512) {
        const int e = (i >= 2560);
        const int ii = i - e * 2560;
        S->cx[0][i] = 0.1f * S->sWsB[e][ii & 255];
    }
    __syncthreads();

    for (int it = 0; it < 3; ++it) {
        if (it > 0) {
            // ===== Phase A-pre + A + B; warp handles groups w and w+16 =====
            #pragma unroll
            for (int gi = 0; gi < 2; gi++) {
                const int g = w + gi * 16;
                float* scr = S->scr[w];

                // --- A-pre: shared WT/bias loads for both elements ---
                {
                    const float4* WTv = reinterpret_cast<const float4*>(g_WT) + g * 320;
                    const float4* vs0 = reinterpret_cast<const float4*>(S->vsum[0]);
                    const float4* vs1 = reinterpret_cast<const float4*>(S->vsum[1]);
                    const int q  = lane & 3;
                    const int jk = lane >> 2;
                    #pragma unroll
                    for (int r = 0; r < 10; r++) {
                        float4 a = WTv[r * 32 + lane];       // coalesced 512B
                        float p0 = dot4(a, vs0[r * 4 + q]);
                        float p1 = dot4(a, vs1[r * 4 + q]);
                        p0 += __shfl_xor_sync(0xffffffffu, p0, 1);
                        p0 += __shfl_xor_sync(0xffffffffu, p0, 2);
                        p1 += __shfl_xor_sync(0xffffffffu, p1, 1);
                        p1 += __shfl_xor_sync(0xffffffffu, p1, 2);
                        if (q == 0) { scr[r * 8 + jk] = p0; scr[96 + r * 8 + jk] = p1; }
                    }
                    const float4* Bv = reinterpret_cast<const float4*>(bias);
                    float4 fa = Bv[g * 40 + lane];
                    float4 fb = Bv[g * 40 + 32 + (lane & 7)];
                    float pa0 = dot4(fa, vs0[lane]);
                    float pa1 = dot4(fa, vs1[lane]);
                    float pb0 = dot4(fb, vs0[32 + (lane & 7)]);
                    float pb1 = dot4(fb, vs1[32 + (lane & 7)]);
                    pa0 += __shfl_xor_sync(0xffffffffu, pa0, 1);
                    pa0 += __shfl_xor_sync(0xffffffffu, pa0, 2);
                    pa1 += __shfl_xor_sync(0xffffffffu, pa1, 1);
                    pa1 += __shfl_xor_sync(0xffffffffu, pa1, 2);
                    pb0 += __shfl_xor_sync(0xffffffffu, pb0, 1);
                    pb0 += __shfl_xor_sync(0xffffffffu, pb0, 2);
                    pb1 += __shfl_xor_sync(0xffffffffu, pb1, 1);
                    pb1 += __shfl_xor_sync(0xffffffffu, pb1, 2);
                    if ((lane & 3) == 0) {
                        scr[80 + (lane >> 2)] = pa0;
                        scr[96 + 80 + (lane >> 2)] = pa1;
                        if (lane < 8) {
                            scr[88 + (lane >> 2)] = pb0;
                            scr[96 + 88 + (lane >> 2)] = pb1;
                        }
                    }
                }
                __syncwarp();

                // --- Phase A+B per element ---
                #pragma unroll
                for (int e = 0; e < 2; e++) {
                    const float* se = scr + e * 96;
                    const float* xge = e ? x1g : x0g;
                    // Phase A: logits -> softmax over j -> c
                    {
                        const float* xr = xge + g * 288;
                        float xv[8], xv2[8];
                        #pragma unroll
                        for (int k = 0; k < 8; k++) {
                            xv[k]  = xr[k * 36 + lane];
                            xv2[k] = xr[k * 36 + 32 + (lane & 3)];
                        }
                        float bb[10], bb2[10];
                        #pragma unroll
                        for (int j = 0; j < 10; j++) {
                            const float4* vwp = reinterpret_cast<const float4*>(se + j * 8);
                            float4 w0 = vwp[0], w1 = vwp[1];
                            float t0 = se[80 + j];
                            float a  = t0, a2 = t0;
                            a  += w0.x*xv[0] + w0.y*xv[1] + w0.z*xv[2] + w0.w*xv[3]
                                + w1.x*xv[4] + w1.y*xv[5] + w1.z*xv[6] + w1.w*xv[7];
                            a2 += w0.x*xv2[0] + w0.y*xv2[1] + w0.z*xv2[2] + w0.w*xv2[3]
                                + w1.x*xv2[4] + w1.y*xv2[5] + w1.z*xv2[6] + w1.w*xv2[7];
                            bb[j] = a; bb2[j] = a2;
                        }
                        float Z = 0.f, Z2 = 0.f;
                        #pragma unroll
                        for (int j = 0; j < 10; j++) {
                            bb[j]  = ex2_approx(bb[j]);   Z  += bb[j];
                            bb2[j] = ex2_approx(bb2[j]);  Z2 += bb2[j];
                        }
                        float r  = rcp_approx(Z);
                        float r2 = rcp_approx(Z2);
                        float* cw = S->cbuf[w];
                        #pragma unroll
                        for (int j = 0; j < 10; j++) {
                            cw[j * 36 + lane] = bb[j] * r;
                            if (lane < 4) cw[j * 36 + 32 + lane] = bb2[j] * r2;
                        }
                    }
                    __syncwarp();
                    // Phase B: cx[e][j][g][k] = sum_hw c*x ; csum[e][j][g]
                    {
                        const int k = lane >> 2, q = lane & 3;
                        const float* xr = xge + (g * 8 + k) * 36;
                        float4 x0 = *reinterpret_cast<const float4*>(xr + 4 * q);
                        float4 x1 = *reinterpret_cast<const float4*>(xr + 16 + 4 * q);
                        float  x2 = xr[32 + q];
                        const float* cb = S->cbuf[w];
                        float acc[10], cs[10];
                        #pragma unroll
                        for (int j = 0; j < 10; j++) {
                            float4 c0 = *reinterpret_cast<const float4*>(cb + j * 36 + 4 * q);
                            float4 c1 = *reinterpret_cast<const float4*>(cb + j * 36 + 16 + 4 * q);
                            float  c2 = cb[j * 36 + 32 + q];
                            acc[j] = dot4(c0, x0) + dot4(c1, x1) + c2 * x2;
                            cs[j]  = sum4(c0) + sum4(c1) + c2;
                        }
                        #pragma unroll
                        for (int j = 0; j < 10; j++) {
                            acc[j] += __shfl_xor_sync(0xffffffffu, acc[j], 1);
                            acc[j] += __shfl_xor_sync(0xffffffffu, acc[j], 2);
                            cs[j]  += __shfl_xor_sync(0xffffffffu, cs[j], 1);
                            cs[j]  += __shfl_xor_sync(0xffffffffu, cs[j], 2);
                        }
                        if (q == 0) {
                            #pragma unroll
                            for (int j = 0; j < 10; j++) S->cx[e][j * 256 + g * 8 + k] = acc[j];
                            if (k == 0) {
                                #pragma unroll
                                for (int j = 0; j < 10; j++) S->csum[e][j * 32 + g] = cs[j];
                            }
                        }
                    }
                    __syncwarp();
                }
            }
            __syncthreads();
        }

        // ===== Phase C: shared W/bias loads serve both elements =====
        if (tid < 320) {
            const int p  = tid >> 1;
            const int kh = tid & 1;
            const int j  = p >> 4;
            const float4* Wv   = reinterpret_cast<const float4*>(W);
            const float4* cxv0 = reinterpret_cast<const float4*>(S->cx[0]);
            const float4* cxv1 = reinterpret_cast<const float4*>(S->cx[1]);
            float a00 = 0.f, a01 = 0.f, a10 = 0.f, a11 = 0.f;
            #pragma unroll 8
            for (int g = 0; g < 32; g += 2) {
                float4 w0 = Wv[g * 320 + p * 2 + kh];
                float4 w1 = Wv[(g + 1) * 320 + p * 2 + kh];
                a00 += dot4(w0, cxv0[j * 64 + g * 2 + kh]);
                a01 += dot4(w1, cxv0[j * 64 + (g + 1) * 2 + kh]);
                a10 += dot4(w0, cxv1[j * 64 + g * 2 + kh]);
                a11 += dot4(w1, cxv1[j * 64 + (g + 1) * 2 + kh]);
            }
            float acc0 = a00 + a01, acc1 = a10 + a11;
            acc0 += __shfl_xor_sync(0xffffffffu, acc0, 1);
            acc1 += __shfl_xor_sync(0xffffffffu, acc1, 1);
            if (kh == 0) { S->sWsB[0][p] = acc0; S->sWsB[1][p] = acc1; }
        } else if (tid >= 352) {
            const int p = tid - 352;     // 0..159
            const int j = p >> 4;
            float ab0, ab1;
            if (it == 0) {
                // csum == 3.6 uniformly: sB = 3.6 * sum_g bias[g][p]
                float sb = 0.f;
                #pragma unroll
                for (int gg = 0; gg < 8; gg++) {
                    sb += bias[(gg * 4 + 0) * 160 + p] + bias[(gg * 4 + 1) * 160 + p]
                        + bias[(gg * 4 + 2) * 160 + p] + bias[(gg * 4 + 3) * 160 + p];
                }
                ab0 = ab1 = 3.6f * sb;
            } else {
                const float4* cs0 = reinterpret_cast<const float4*>(S->csum[0] + j * 32);
                const float4* cs1 = reinterpret_cast<const float4*>(S->csum[1] + j * 32);
                ab0 = 0.f; ab1 = 0.f;
                #pragma unroll
                for (int gg = 0; gg < 8; gg++) {
                    float4 c40 = cs0[gg], c41 = cs1[gg];
                    float bv0 = bias[(gg * 4 + 0) * 160 + p];
                    float bv1 = bias[(gg * 4 + 1) * 160 + p];
                    float bv2 = bias[(gg * 4 + 2) * 160 + p];
                    float bv3 = bias[(gg * 4 + 3) * 160 + p];
                    ab0 += bv0 * c40.x + bv1 * c40.y + bv2 * c40.z + bv3 * c40.w;
                    ab1 += bv0 * c41.x + bv1 * c41.y + bv2 * c41.z + bv3 * c41.w;
                }
            }
            S->sWsB[0][160 + p] = ab0;
            S->sWsB[1][160 + p] = ab1;
        }
        __syncthreads();

        // ===== Phase D: squash + telescoped vsum accumulate =====
        {
            int e = -1, p = 0;
            if (tid < 160) { e = 0; p = tid; }
            else if (tid >= 256 && tid < 416) { e = 1; p = tid - 256; }
            if (e >= 0) {
                float sv = S->sWsB[e][p] + S->sWsB[e][160 + p];
                float n2 = sv * sv;
                n2 += __shfl_xor_sync(0xffffffffu, n2, 1);
                n2 += __shfl_xor_sync(0xffffffffu, n2, 2);
                n2 += __shfl_xor_sync(0xffffffffu, n2, 4);
                n2 += __shfl_xor_sync(0xffffffffu, n2, 8);
                float f  = __fdividef(sqrtf(n2), 1.0f + n2);
                float vv = sv * f;
                if (it == 2) {
                    if (e == 0 || two) out[(size_t)(e ? b1 : b0) * 160 + p] = vv;
                } else {
                    S->vsum[e][p] = (it == 0) ? LOG2E * vv : S->vsum[e][p] + LOG2E * vv;
                }
            }
        }
        if (it < 2) __syncthreads();
    }
}

extern "C" void kernel_launch(void* const* d_in, const int* in_sizes, int n_in,
                              void* d_out, int out_size) {
    const float* x    = (const float*)d_in[0];
    const float* W    = (const float*)d_in[2];
    const float* bias = (const float*)d_in[3];
    float* out = (float*)d_out;

    transpose_W_kernel<<<160, 256>>>(W);

    cudaFuncSetAttribute(caps_kernel,
                         cudaFuncAttributeMaxDynamicSharedMemorySize,
                         (int)sizeof(Smem));
    caps_kernel<<<296, 512, sizeof(Smem)>>>(x, W, bias, out);
}

// round 14
// speedup vs baseline: 1.1447x; 1.1157x over previous
#include <cuda_runtime.h>
#include <cuda_fp16.h>

// CapLayer fused capsule routing. 296 CTAs x 512 threads, 2 CTAs/SM,
// 2 batch elems/CTA. fp16 data streams (x in smem, W/WT in global halves),
// fp32 accumulation everywhere. Telescoped routing logits (no Phase E).
// x:    d_in[0]  float [512][256][6][6]   (channel = g*8+k, g<32, k<8)
// W:    d_in[2]  float [5120][8] ; flat = g*1280 + p*8 + k   (p = j*16+d)
// bias: d_in[3]  float [5120]    ; flat = g*160  + j*16 + d
// out:  float [512][10][16]

#define LOG2E 1.4426950408889634f

__device__ __half g_hW[40960];    // [g][p][k]  (same flat layout as W)
__device__ __half g_hWT[40960];   // [g][j][k][d]  (d contiguous)

struct Smem {
    __half xh[2][9216];   // 36864 B  [e][g][k][hw] fp16
    float cbuf[16][360];  // per-warp c scratch [w][j][hw]
    float scr[16][192];   // per-warp, per-elem 96: [0..79] vW[j][k], [80..89] vb[j]
    float cx[2][2560];    // [e][j][g][k]
    float csum[2][320];   // [e][j][g]  (written by B, read at it>0)
    float sWsB[2][320];   // sW=[0..159], sB=[160..319]; xsum aliases [0..255]
    float vsum[2][160];   // LOG2E * accumulated v, [e][j][d]
};                        // 99072 B (2 CTAs/SM: 198KB <= 227KB)

__device__ __forceinline__ float ex2_approx(float x) {
    float y; asm("ex2.approx.ftz.f32 %0, %1;" : "=f"(y) : "f"(x)); return y;
}
__device__ __forceinline__ float rcp_approx(float x) {
    float y; asm("rcp.approx.ftz.f32 %0, %1;" : "=f"(y) : "f"(x)); return y;
}
__device__ __forceinline__ float dot4(float4 a, float4 b) {
    return a.x * b.x + a.y * b.y + a.z * b.z + a.w * b.w;
}
__device__ __forceinline__ float sum4(float4 a) {
    return a.x + a.y + a.z + a.w;
}
// 8 halves (uint4) -> two float4
__device__ __forceinline__ void h8_to_f(uint4 h, float4& lo, float4& hi) {
    const __half2* hp = reinterpret_cast<const __half2*>(&h);
    float2 f0 = __half22float2(hp[0]);
    float2 f1 = __half22float2(hp[1]);
    float2 f2 = __half22float2(hp[2]);
    float2 f3 = __half22float2(hp[3]);
    lo = make_float4(f0.x, f0.y, f1.x, f1.y);
    hi = make_float4(f2.x, f2.y, f3.x, f3.y);
}
// 4 halves (uint2) -> float4
__device__ __forceinline__ float4 h4_to_f(uint2 u) {
    const __half2* hp = reinterpret_cast<const __half2*>(&u);
    float2 f0 = __half22float2(hp[0]);
    float2 f1 = __half22float2(hp[1]);
    return make_float4(f0.x, f0.y, f1.x, f1.y);
}

__global__ void prep_W_kernel(const float* __restrict__ W) {
    int i = blockIdx.x * 256 + threadIdx.x;
    if (i < 40960) {
        float v = W[i];                 // i = g*1280 + j*128 + d*8 + k
        g_hW[i] = __float2half(v);
        int k = i & 7, d = (i >> 3) & 15;
        int gj128 = i & ~127;           // g*1280 + j*128 (block is 128 floats!)
        g_hWT[gj128 + k * 16 + d] = __float2half(v);
    }
}

__global__ __launch_bounds__(512, 2)
void caps_kernel(const float* __restrict__ x_g,
                 const float* __restrict__ W,
                 const float* __restrict__ bias,
                 float* __restrict__ out) {
    extern __shared__ float smem_raw[];
    Smem* S = reinterpret_cast<Smem*>(smem_raw);

    const int cta  = blockIdx.x;
    const bool two = (cta < 216);
    const int b0   = two ? cta * 2 : 432 + (cta - 216);
    const int b1   = two ? b0 + 1 : b0;
    const int tid  = threadIdx.x;
    const int w    = tid >> 5;
    const int lane = tid & 31;

    const float* x0g = x_g + (size_t)b0 * 9216;
    const float* x1g = x_g + (size_t)b1 * 9216;

    // ---- load x (coalesced float4), convert to fp16, store to smem ----
    for (int i = tid; i < 2304; i += 512) {
        float4 v0 = reinterpret_cast<const float4*>(x0g)[i];
        float4 v1 = reinterpret_cast<const float4*>(x1g)[i];
        __half2 a0 = __floats2half2_rn(v0.x, v0.y);
        __half2 b0h = __floats2half2_rn(v0.z, v0.w);
        __half2 a1 = __floats2half2_rn(v1.x, v1.y);
        __half2 b1h = __floats2half2_rn(v1.z, v1.w);
        uint2 u0, u1;
        u0.x = *reinterpret_cast<unsigned*>(&a0);
        u0.y = *reinterpret_cast<unsigned*>(&b0h);
        u1.x = *reinterpret_cast<unsigned*>(&a1);
        u1.y = *reinterpret_cast<unsigned*>(&b1h);
        *reinterpret_cast<uint2*>(&S->xh[0][4 * i]) = u0;
        *reinterpret_cast<uint2*>(&S->xh[1][4 * i]) = u1;
    }
    __syncthreads();

    // ---- xsum[e][g][k] = sum_hw x (fp16 source, fp32 accum) ----
    {
        const int e = tid >> 8, idx = tid & 255;
        const __half2* p = reinterpret_cast<const __half2*>(S->xh[e] + idx * 36);
        float acc = 0.f;
        #pragma unroll
        for (int t = 0; t < 18; t++) {
            float2 f = __half22float2(p[t]);
            acc += f.x + f.y;
        }
        S->sWsB[e][idx] = acc;
    }
    __syncthreads();

    // iter 1 shortcut: c uniform 0.1 -> cx = 0.1*xsum (all j)
    for (int i = tid; i < 5120; i += 512) {
        const int e = (i >= 2560);
        const int ii = i - e * 2560;
        S->cx[0][i] = 0.1f * S->sWsB[e][ii & 255];
    }
    __syncthreads();

    for (int it = 0; it < 3; ++it) {
        if (it > 0) {
            // ===== Phase A-pre + A + B; warp handles groups w and w+16 =====
            #pragma unroll
            for (int gi = 0; gi < 2; gi++) {
                const int g = w + gi * 16;
                float* scr = S->scr[w];

                // --- A-pre: fp16 WT, 2 j per round; shared loads for both elems ---
                {
                    const __half* hWT = g_hWT + g * 1280;
                    const float4* vs0 = reinterpret_cast<const float4*>(S->vsum[0]);
                    const float4* vs1 = reinterpret_cast<const float4*>(S->vsum[1]);
                    const int jj = lane >> 4;         // 0/1: which j of the pair
                    const int kk = (lane & 15) >> 1;  // k 0..7
                    const int dh = lane & 1;          // d half: 0 -> d0..7, 1 -> d8..15
                    #pragma unroll
                    for (int r = 0; r < 5; r++) {
                        const int j = 2 * r + jj;
                        uint4 h = *reinterpret_cast<const uint4*>(
                            hWT + j * 128 + kk * 16 + dh * 8);   // 512B/warp coalesced
                        float4 lo, hi;
                        h8_to_f(h, lo, hi);
                        float4 va0 = vs0[j * 4 + dh * 2], vb0 = vs0[j * 4 + dh * 2 + 1];
                        float4 va1 = vs1[j * 4 + dh * 2], vb1 = vs1[j * 4 + dh * 2 + 1];
                        float p0 = dot4(lo, va0) + dot4(hi, vb0);
                        float p1 = dot4(lo, va1) + dot4(hi, vb1);
                        p0 += __shfl_xor_sync(0xffffffffu, p0, 1);
                        p1 += __shfl_xor_sync(0xffffffffu, p1, 1);
                        if (dh == 0) {
                            scr[j * 8 + kk]      = p0;
                            scr[96 + j * 8 + kk] = p1;
                        }
                    }
                    // vb[j] = vsum . bias[g] (fp32 bias, contiguous block)
                    const float4* Bv = reinterpret_cast<const float4*>(bias);
                    float4 fa = Bv[g * 40 + lane];
                    float4 fb = Bv[g * 40 + 32 + (lane & 7)];
                    float pa0 = dot4(fa, vs0[lane]);
                    float pa1 = dot4(fa, vs1[lane]);
                    float pb0 = dot4(fb, vs0[32 + (lane & 7)]);
                    float pb1 = dot4(fb, vs1[32 + (lane & 7)]);
                    pa0 += __shfl_xor_sync(0xffffffffu, pa0, 1);
                    pa0 += __shfl_xor_sync(0xffffffffu, pa0, 2);
                    pa1 += __shfl_xor_sync(0xffffffffu, pa1, 1);
                    pa1 += __shfl_xor_sync(0xffffffffu, pa1, 2);
                    pb0 += __shfl_xor_sync(0xffffffffu, pb0, 1);
                    pb0 += __shfl_xor_sync(0xffffffffu, pb0, 2);
                    pb1 += __shfl_xor_sync(0xffffffffu, pb1, 1);
                    pb1 += __shfl_xor_sync(0xffffffffu, pb1, 2);
                    if ((lane & 3) == 0) {
                        scr[80 + (lane >> 2)] = pa0;
                        scr[96 + 80 + (lane >> 2)] = pa1;
                        if (lane < 8) {
                            scr[88 + (lane >> 2)] = pb0;
                            scr[96 + 88 + (lane >> 2)] = pb1;
                        }
                    }
                }
                __syncwarp();

                // --- Phase A+B per element (x fp16 from smem) ---
                #pragma unroll
                for (int e = 0; e < 2; e++) {
                    const float* se = scr + e * 96;
                    const __half* xge = S->xh[e];
                    // Phase A: logits -> softmax over j -> c
                    {
                        const __half* xr = xge + g * 288;
                        float xv[8], xv2[8];
                        #pragma unroll
                        for (int k = 0; k < 8; k++) {
                            xv[k]  = __half2float(xr[k * 36 + lane]);
                            xv2[k] = __half2float(xr[k * 36 + 32 + (lane & 3)]);
                        }
                        float bb[10], bb2[10];
                        #pragma unroll
                        for (int j = 0; j < 10; j++) {
                            const float4* vwp = reinterpret_cast<const float4*>(se + j * 8);
                            float4 w0 = vwp[0], w1 = vwp[1];   // broadcast
                            float t0 = se[80 + j];
                            float a  = t0, a2 = t0;
                            a  += w0.x*xv[0] + w0.y*xv[1] + w0.z*xv[2] + w0.w*xv[3]
                                + w1.x*xv[4] + w1.y*xv[5] + w1.z*xv[6] + w1.w*xv[7];
                            a2 += w0.x*xv2[0] + w0.y*xv2[1] + w0.z*xv2[2] + w0.w*xv2[3]
                                + w1.x*xv2[4] + w1.y*xv2[5] + w1.z*xv2[6] + w1.w*xv2[7];
                            bb[j] = a; bb2[j] = a2;
                        }
                        float Z = 0.f, Z2 = 0.f;
                        #pragma unroll
                        for (int j = 0; j < 10; j++) {
                            bb[j]  = ex2_approx(bb[j]);   Z  += bb[j];
                            bb2[j] = ex2_approx(bb2[j]);  Z2 += bb2[j];
                        }
                        float r  = rcp_approx(Z);
                        float r2 = rcp_approx(Z2);
                        float* cw = S->cbuf[w];
                        #pragma unroll
                        for (int j = 0; j < 10; j++) {
                            cw[j * 36 + lane] = bb[j] * r;
                            if (lane < 4) cw[j * 36 + 32 + lane] = bb2[j] * r2;
                        }
                    }
                    __syncwarp();
                    // Phase B: cx[e][j][g][k] = sum_hw c*x ; csum[e][j][g]
                    {
                        const int k = lane >> 2, q = lane & 3;
                        const __half* xr = xge + (g * 8 + k) * 36;
                        float4 x0 = h4_to_f(*reinterpret_cast<const uint2*>(xr + 4 * q));
                        float4 x1 = h4_to_f(*reinterpret_cast<const uint2*>(xr + 16 + 4 * q));
                        float  x2 = __half2float(xr[32 + q]);
                        const float* cb = S->cbuf[w];
                        float acc[10], cs[10];
                        #pragma unroll
                        for (int j = 0; j < 10; j++) {
                            float4 c0 = *reinterpret_cast<const float4*>(cb + j * 36 + 4 * q);
                            float4 c1 = *reinterpret_cast<const float4*>(cb + j * 36 + 16 + 4 * q);
                            float  c2 = cb[j * 36 + 32 + q];
                            acc[j] = dot4(c0, x0) + dot4(c1, x1) + c2 * x2;
                            cs[j]  = sum4(c0) + sum4(c1) + c2;
                        }
                        #pragma unroll
                        for (int j = 0; j < 10; j++) {
                            acc[j] += __shfl_xor_sync(0xffffffffu, acc[j], 1);
                            acc[j] += __shfl_xor_sync(0xffffffffu, acc[j], 2);
                            cs[j]  += __shfl_xor_sync(0xffffffffu, cs[j], 1);
                            cs[j]  += __shfl_xor_sync(0xffffffffu, cs[j], 2);
                        }
                        if (q == 0) {
                            #pragma unroll
                            for (int j = 0; j < 10; j++) S->cx[e][j * 256 + g * 8 + k] = acc[j];
                            if (k == 0) {
                                #pragma unroll
                                for (int j = 0; j < 10; j++) S->csum[e][j * 32 + g] = cs[j];
                            }
                        }
                    }
                    __syncwarp();
                }
            }
            __syncthreads();
        }

        // ===== Phase C: fp16 W, one 16B load = all 8 k; both elements =====
        if (tid < 320) {
            const int p  = tid >> 1;
            const int gh = tid & 1;      // g parity
            const int j  = p >> 4;
            const float4* cxv0 = reinterpret_cast<const float4*>(S->cx[0]);
            const float4* cxv1 = reinterpret_cast<const float4*>(S->cx[1]);
            float acc0 = 0.f, acc1 = 0.f;
            #pragma unroll 8
            for (int gg = 0; gg < 16; gg++) {
                const int g = gg * 2 + gh;
                uint4 h = *reinterpret_cast<const uint4*>(&g_hW[g * 1280 + p * 8]);
                float4 lo, hi;
                h8_to_f(h, lo, hi);
                acc0 += dot4(lo, cxv0[j * 64 + g * 2]) + dot4(hi, cxv0[j * 64 + g * 2 + 1]);
                acc1 += dot4(lo, cxv1[j * 64 + g * 2]) + dot4(hi, cxv1[j * 64 + g * 2 + 1]);
            }
            acc0 += __shfl_xor_sync(0xffffffffu, acc0, 1);
            acc1 += __shfl_xor_sync(0xffffffffu, acc1, 1);
            if (gh == 0) { S->sWsB[0][p] = acc0; S->sWsB[1][p] = acc1; }
        } else if (tid >= 352) {
            const int p = tid - 352;     // 0..159
            const int j = p >> 4;
            float ab0, ab1;
            if (it == 0) {
                float sb = 0.f;
                #pragma unroll
                for (int gg = 0; gg < 8; gg++) {
                    sb += bias[(gg * 4 + 0) * 160 + p] + bias[(gg * 4 + 1) * 160 + p]
                        + bias[(gg * 4 + 2) * 160 + p] + bias[(gg * 4 + 3) * 160 + p];
                }
                ab0 = ab1 = 3.6f * sb;
            } else {
                const float4* cs0 = reinterpret_cast<const float4*>(S->csum[0] + j * 32);
                const float4* cs1 = reinterpret_cast<const float4*>(S->csum[1] + j * 32);
                ab0 = 0.f; ab1 = 0.f;
                #pragma unroll
                for (int gg = 0; gg < 8; gg++) {
                    float4 c40 = cs0[gg], c41 = cs1[gg];
                    float bv0 = bias[(gg * 4 + 0) * 160 + p];
                    float bv1 = bias[(gg * 4 + 1) * 160 + p];
                    float bv2 = bias[(gg * 4 + 2) * 160 + p];
                    float bv3 = bias[(gg * 4 + 3) * 160 + p];
                    ab0 += bv0 * c40.x + bv1 * c40.y + bv2 * c40.z + bv3 * c40.w;
                    ab1 += bv0 * c41.x + bv1 * c41.y + bv2 * c41.z + bv3 * c41.w;
                }
            }
            S->sWsB[0][160 + p] = ab0;
            S->sWsB[1][160 + p] = ab1;
        }
        __syncthreads();

        // ===== Phase D: squash + telescoped vsum accumulate =====
        {
            int e = -1, p = 0;
            if (tid < 160) { e = 0; p = tid; }
            else if (tid >= 256 && tid < 416) { e = 1; p = tid - 256; }
            if (e >= 0) {
                float sv = S->sWsB[e][p] + S->sWsB[e][160 + p];
                float n2 = sv * sv;
                n2 += __shfl_xor_sync(0xffffffffu, n2, 1);
                n2 += __shfl_xor_sync(0xffffffffu, n2, 2);
                n2 += __shfl_xor_sync(0xffffffffu, n2, 4);
                n2 += __shfl_xor_sync(0xffffffffu, n2, 8);
                float f  = __fdividef(sqrtf(n2), 1.0f + n2);
                float vv = sv * f;
                if (it == 2) {
                    if (e == 0 || two) out[(size_t)(e ? b1 : b0) * 160 + p] = vv;
                } else {
                    S->vsum[e][p] = (it == 0) ? LOG2E * vv : S->vsum[e][p] + LOG2E * vv;
                }
            }
        }
        if (it < 2) __syncthreads();
    }
}

extern "C" void kernel_launch(void* const* d_in, const int* in_sizes, int n_in,
                              void* d_out, int out_size) {
    const float* x    = (const float*)d_in[0];
    const float* W    = (const float*)d_in[2];
    const float* bias = (const float*)d_in[3];
    float* out = (float*)d_out;

    prep_W_kernel<<<160, 256>>>(W);

    cudaFuncSetAttribute(caps_kernel,
                         cudaFuncAttributeMaxDynamicSharedMemorySize,
                         (int)sizeof(Smem));
    caps_kernel<<<296, 512, sizeof(Smem)>>>(x, W, bias, out);
}